// round 14
// baseline (speedup 1.0000x reference)
#include <cuda_runtime.h>

// ---------------- problem constants ----------------------------------------
#define CNUM   10000
#define KNUM   5
#define NNODES 50000
#define EMBD   200
#define FDIM   64
#define LNUM   3
#define HNUM   3
#define HID    256

#define NBLK   98        // chunks per head (3*98 = 294 blocks ~= 2/SM)
#define CHUNK  103       // crystals per chunk (98*103 >= 10000)
#define BATCH  8         // crystals per batch
#define NTHR   256

typedef unsigned long long ull;

__device__ __forceinline__ ull dup2(float x) {
    ull r; asm("mov.b64 %0, {%1, %1};" : "=l"(r) : "f"(x)); return r;
}
__device__ __forceinline__ void fma2(ull &d, ull a, ull b) {
    asm("fma.rn.f32x2 %0, %1, %2, %0;" : "+l"(d) : "l"(a), "l"(b));
}
__device__ __forceinline__ float2 unpack2(ull v) {
    float2 r; asm("mov.b64 {%0, %1}, %2;" : "=f"(r.x), "=f"(r.y) : "l"(v)); return r;
}
union F4U { float4 f; ull u[2]; float s[4]; };

// ---------------- static device scratch ------------------------------------
__device__ float g_X[(size_t)NNODES * FDIM];
__device__ float g_hout[HNUM][(size_t)NNODES * FDIM];
__device__ float g_pool[HNUM][(size_t)CNUM * FDIM];

// ---------------- smem layout (floats) -------------------------------------
#define S_XS   0            // 40 x 64   = 2560
#define S_A    2560         // 40 x 256  = 10240
#define S_B    12800        // 40 x 256  = 10240
#define S_B1G  23040        // 256
#define S_W2G  23296        // 256
#define S_B1M  23552        // 256
#define S_GATE 23808        // 8 x 32
#define S_AW   24064        // 8 x 32
#define S_SAS  24320        // 64
#define S_WNS  24384        // 2 x 64 (parity; edge uses slot 0 only)
#define S_GM   24512        // 8 x 256 (pool combine target)
#define FE_SMEM ((24512 + 2048 + 32) * 4)   // ~106.4 KB -> 2 CTAs/SM

// ---------------- kernel 1: embedding (8 nodes / block) --------------------
#define EMB_SMEM ((12608 + 1600) * 4)
__global__ void embed_kernel(const float* __restrict__ ef,
                             const float* __restrict__ W,
                             const float* __restrict__ b,
                             const float* __restrict__ ew) {
    extern __shared__ float sm[];
    float* Wsm = sm;
    float* Xs  = sm + 12608;
    const int tid = threadIdx.x;
    const int n0 = blockIdx.x * 8;
    for (int i = tid; i < 12600; i += 512) Wsm[i] = W[i];
    for (int i = tid; i < 1600; i += 512)
        Xs[i] = ef[(size_t)(n0 + (i / 200)) * EMBD + (i % 200)];
    __syncthreads();
    const int n = tid >> 6, f = tid & 63;
    if (f < 63) {
        float acc = b[f];
        const float* xr = &Xs[n * 200];
        #pragma unroll 8
        for (int e = 0; e < EMBD; e++) acc += xr[e] * Wsm[e * 63 + f];
        g_X[(size_t)(n0 + n) * FDIM + f] = acc;
    } else {
        g_X[(size_t)(n0 + n) * FDIM + 63] = ew[n0 + n];
    }
}

// ---- gemm40h: [40,64] @ [64,256] -> smem; 8 warps: (col-half, row-group) ---
// warp owns 128 columns (wh) x 10 rows (wr + 4*i); same warp tile as gemm80.
__device__ __noinline__ void gemm40h(const float* __restrict__ Xs,
                                     const float* __restrict__ W,
                                     float* __restrict__ out,
                                     int lane, int wr, int wh) {
    const float* Wp = W + wh * 128 + 4 * lane;
    ull acc[10][2];
    #pragma unroll
    for (int i = 0; i < 10; i++) { acc[i][0] = 0ull; acc[i][1] = 0ull; }

    for (int k4 = 0; k4 < 64; k4 += 4) {
        float4 a[10];
        #pragma unroll
        for (int i = 0; i < 10; i++)
            a[i] = *(const float4*)&Xs[(wr + 4 * i) * 64 + k4];
        #pragma unroll
        for (int kk = 0; kk < 4; kk++) {
            F4U w; w.f = *(const float4*)&Wp[(k4 + kk) * 256];
            #pragma unroll
            for (int i = 0; i < 10; i++) {
                float av = kk == 0 ? a[i].x : kk == 1 ? a[i].y : kk == 2 ? a[i].z : a[i].w;
                ull ad = dup2(av);
                fma2(acc[i][0], ad, w.u[0]);
                fma2(acc[i][1], ad, w.u[1]);
            }
        }
    }
    #pragma unroll
    for (int i = 0; i < 10; i++) {
        F4U o;
        o.u[0] = acc[i][0]; o.u[1] = acc[i][1];
        *(float4*)&out[(wr + 4 * i) * 256 + wh * 128 + 4 * lane] = o.f;
    }
}

// ---------------- kernel 2: fused proj + edge attention --------------------
__global__ void __launch_bounds__(NTHR, 2)
fused_edge(const float* __restrict__ gW1, const float* __restrict__ gb1,
           const float* __restrict__ gW2, const float* __restrict__ gb2,
           const float* __restrict__ mW1, const float* __restrict__ mb1,
           const float* __restrict__ mW2, const float* __restrict__ mb2,
           const float* __restrict__ gpow, const float* __restrict__ ew) {
    extern __shared__ float sm[];
    float* Xs    = sm + S_XS;
    float* A     = sm + S_A;
    float* B     = sm + S_B;
    float* b1g_s = sm + S_B1G;
    float* w2g_s = sm + S_W2G;
    float* b1m_s = sm + S_B1M;
    float* gateb = sm + S_GATE;
    float* awb   = sm + S_AW;
    float* sas   = sm + S_SAS;
    float* wns   = sm + S_WNS;

    const int tid  = threadIdx.x;
    const int warp = tid >> 5, lane = tid & 31;
    const int wr = warp & 3, wh = warp >> 2;
    const int h     = blockIdx.x / NBLK;
    const int chunk = blockIdx.x % NBLK;
    const int cbeg = chunk * CHUNK;
    const int cend = min(cbeg + CHUNK, CNUM);

    const float* WgA = gW1 + (size_t)h * 128 * 256;
    const float* WgB = WgA + 64 * 256;
    const float* WmA = mW1 + (size_t)h * 128 * 256;
    const float* WmB = WmA + 64 * 256;
    const float* W2h = mW2 + (size_t)h * 256 * 64;

    b1g_s[tid] = gb1[h * 256 + tid];
    w2g_s[tid] = gW2[h * 256 + tid];
    b1m_s[tid] = mb1[h * 256 + tid];
    const float p    = gpow[h];
    const float b2gv = gb2[h];
    const float2 b2r = *(const float2*)&mb2[h * 64 + 2 * lane];
    float* hout = g_hout[h];

    // prologue: stage first batch
    {
        const int nrow0 = (cend - cbeg < BATCH ? cend - cbeg : BATCH) * 5;
        for (int idx = tid; idx < 640; idx += NTHR) {
            int r = idx >> 4;
            if (r < nrow0)
                *(float4*)&Xs[r * 64 + (idx & 15) * 4] =
                    *(const float4*)&g_X[(size_t)(cbeg * 5 + r) * 64 + (idx & 15) * 4];
        }
        if (tid < 64) {
            int w = tid >> 3, j = tid & 7;
            if (j < 5 && cbeg + w < cend)
                wns[tid] = powf(ew[(cbeg + w) * 5 + j], p);
        }
    }

    for (int cb = cbeg; cb < cend; cb += BATCH) {
        __syncthreads();   // staging visible + WAR on A,B

        // gate projections
        gemm40h(Xs, WgA, A, lane, wr, wh);
        gemm40h(Xs, WgB, B, lane, wr, wh);
        __syncthreads();

        // gate + softmax: warp <-> crystal; B rows cached in registers
        {
            const int cc = warp;
            if (cb + cc < cend) {
                float w2g_r[8], b_r[5][8];
                #pragma unroll
                for (int t = 0; t < 8; t++) w2g_r[t] = w2g_s[lane + 32 * t];
                #pragma unroll
                for (int j = 0; j < 5; j++)
                    #pragma unroll
                    for (int t = 0; t < 8; t++)
                        b_r[j][t] = B[(cc * 5 + j) * 256 + lane + 32 * t];
                #pragma unroll
                for (int i = 0; i < 5; i++) {
                    float gsr[8];
                    #pragma unroll
                    for (int t = 0; t < 8; t++) {
                        int k = lane + 32 * t;
                        gsr[t] = A[(cc * 5 + i) * 256 + k] + b1g_s[k];
                    }
                    #pragma unroll
                    for (int j = 0; j < 5; j++) {
                        float a = 0.f;
                        #pragma unroll
                        for (int t = 0; t < 8; t++) {
                            float hv = gsr[t] + b_r[j][t];
                            hv = hv >= 0.f ? hv : 0.01f * hv;
                            a += hv * w2g_r[t];
                        }
                        #pragma unroll
                        for (int o = 16; o; o >>= 1) a += __shfl_xor_sync(0xffffffffu, a, o);
                        if (lane == 0) gateb[cc * 32 + i * 5 + j] = a + b2gv;
                    }
                }
                __syncwarp();
                if (lane < 5) {
                    int i = lane;
                    float mx = -1e30f;
                    #pragma unroll
                    for (int j = 0; j < 5; j++) mx = fmaxf(mx, gateb[cc * 32 + i * 5 + j]);
                    float v[5], s = 0.f;
                    #pragma unroll
                    for (int j = 0; j < 5; j++) {
                        v[j] = wns[cc * 8 + j] * expf(gateb[cc * 32 + i * 5 + j] - mx);
                        s += v[j];
                    }
                    float inv = 1.f / (s + 1e-10f);
                    float sa = 0.f;
                    #pragma unroll
                    for (int j = 0; j < 5; j++) { float a = v[j] * inv; awb[cc * 32 + i * 5 + j] = a; sa += a; }
                    sas[cc * 5 + i] = sa;
                }
            }
        }
        __syncthreads();

        // msg projections (overwrite A,B)
        gemm40h(Xs, WmA, A, lane, wr, wh);
        gemm40h(Xs, WmB, B, lane, wr, wh);
        __syncthreads();   // Xs now dead for this batch

        // overlap phase: prefetch next batch's X/wns + G build (warp-local)
        {
            const int cb2 = cb + BATCH;
            if (cb2 < cend) {
                const int nrow2 = (cend - cb2 < BATCH ? cend - cb2 : BATCH) * 5;
                for (int idx = tid; idx < 640; idx += NTHR) {
                    int r = idx >> 4;
                    if (r < nrow2)
                        *(float4*)&Xs[r * 64 + (idx & 15) * 4] =
                            *(const float4*)&g_X[(size_t)(cb2 * 5 + r) * 64 + (idx & 15) * 4];
                }
                if (tid < 64) {
                    int w = tid >> 3, j = tid & 7;
                    if (j < 5 && cb2 + w < cend)
                        wns[tid] = powf(ew[(cb2 + w) * 5 + j], p);
                }
            }

            const int cc = warp;
            if (cb + cc < cend) {
                float a_r[25];
                #pragma unroll
                for (int q = 0; q < 25; q++) a_r[q] = awb[cc * 32 + q];
                #pragma unroll
                for (int t = 0; t < 8; t++) {
                    int k = lane + 32 * t;
                    float bm = b1m_s[k];
                    float s0 = A[(cc * 5 + 0) * 256 + k] + bm;
                    float s1 = A[(cc * 5 + 1) * 256 + k] + bm;
                    float s2 = A[(cc * 5 + 2) * 256 + k] + bm;
                    float s3 = A[(cc * 5 + 3) * 256 + k] + bm;
                    float s4 = A[(cc * 5 + 4) * 256 + k] + bm;
                    float g0 = 0.f, g1 = 0.f, g2 = 0.f, g3 = 0.f, g4 = 0.f;
                    #pragma unroll
                    for (int j = 0; j < 5; j++) {
                        float nb = B[(cc * 5 + j) * 256 + k];
                        float hv;
                        hv = s0 + nb; hv = hv >= 0.f ? hv : 0.01f * hv; g0 += a_r[0 * 5 + j] * hv;
                        hv = s1 + nb; hv = hv >= 0.f ? hv : 0.01f * hv; g1 += a_r[1 * 5 + j] * hv;
                        hv = s2 + nb; hv = hv >= 0.f ? hv : 0.01f * hv; g2 += a_r[2 * 5 + j] * hv;
                        hv = s3 + nb; hv = hv >= 0.f ? hv : 0.01f * hv; g3 += a_r[3 * 5 + j] * hv;
                        hv = s4 + nb; hv = hv >= 0.f ? hv : 0.01f * hv; g4 += a_r[4 * 5 + j] * hv;
                    }
                    A[(cc * 5 + 0) * 256 + k] = g0;
                    A[(cc * 5 + 1) * 256 + k] = g1;
                    A[(cc * 5 + 2) * 256 + k] = g2;
                    A[(cc * 5 + 3) * 256 + k] = g3;
                    A[(cc * 5 + 4) * 256 + k] = g4;
                }
            }
        }
        __syncwarp();      // G rows are same-warp: no CTA barrier needed

        // final GEMM: warp owns its crystal's 5 G rows (written by itself)
        {
            ull acc[5];
            #pragma unroll
            for (int i = 0; i < 5; i++) acc[i] = 0ull;
            #pragma unroll 2
            for (int k4 = 0; k4 < 256; k4 += 4) {
                ull w[4];
                #pragma unroll
                for (int kk = 0; kk < 4; kk++)
                    w[kk] = *(const ull*)&W2h[(k4 + kk) * 64 + 2 * lane];
                #pragma unroll
                for (int i = 0; i < 5; i++) {
                    F4U g; g.f = *(const float4*)&A[(5 * warp + i) * 256 + k4];
                    fma2(acc[i], dup2(g.s[0]), w[0]);
                    fma2(acc[i], dup2(g.s[1]), w[1]);
                    fma2(acc[i], dup2(g.s[2]), w[2]);
                    fma2(acc[i], dup2(g.s[3]), w[3]);
                }
            }
            if (cb + warp < cend) {
                #pragma unroll
                for (int i = 0; i < 5; i++) {
                    int r = 5 * warp + i;
                    float2 av = unpack2(acc[i]);
                    float sa = sas[r];
                    float2 o = make_float2(av.x + sa * b2r.x, av.y + sa * b2r.y);
                    *(float2*)&hout[(size_t)(cb * 5 + r) * 64 + 2 * lane] = o;
                }
            }
        }
        // no barrier: loop-top __syncthreads covers WAR on A,B and staging
    }
}

// ---------------- kernel 3: residual combine over heads --------------------
__global__ void combine_layer() {
    size_t i = (size_t)blockIdx.x * 256 + threadIdx.x;
    if (i < (size_t)NNODES * FDIM)
        g_X[i] += (g_hout[0][i] + g_hout[1][i] + g_hout[2][i]) * (1.f / 3.f);
}

// ---------------- kernel 4: fused proj + pool ------------------------------
__global__ void __launch_bounds__(NTHR, 2)
fused_pool(const float* __restrict__ gW1, const float* __restrict__ gb1,
           const float* __restrict__ gW2, const float* __restrict__ gb2,
           const float* __restrict__ mW1, const float* __restrict__ mb1,
           const float* __restrict__ mW2, const float* __restrict__ mb2,
           const float* __restrict__ cpow, const float* __restrict__ ew) {
    extern __shared__ float sm[];
    float* Xs    = sm + S_XS;
    float* A     = sm + S_A;
    float* B     = sm + S_B;
    float* b1g_s = sm + S_B1G;
    float* w2g_s = sm + S_W2G;
    float* b1m_s = sm + S_B1M;
    float* gateb = sm + S_GATE;
    float* awb   = sm + S_AW;
    float* sas   = sm + S_SAS;
    float* wns   = sm + S_WNS;   // 2 x 64: read slot par, prefetch writes par^1
    float* GM    = sm + S_GM;

    const int tid  = threadIdx.x;
    const int warp = tid >> 5, lane = tid & 31;
    const int wr = warp & 3, wh = warp >> 2;
    const int h     = blockIdx.x / NBLK;
    const int chunk = blockIdx.x % NBLK;
    const int cbeg = chunk * CHUNK;
    const int cend = min(cbeg + CHUNK, CNUM);

    const float* W1g = gW1 + (size_t)h * 64 * 256;
    const float* W1m = mW1 + (size_t)h * 64 * 256;
    const float* W2h = mW2 + (size_t)h * 256 * 64;

    b1g_s[tid] = gb1[h * 256 + tid];
    w2g_s[tid] = gW2[h * 256 + tid];
    b1m_s[tid] = mb1[h * 256 + tid];
    const float p    = cpow[h];
    const float b2gv = gb2[h];
    const float2 b2r = *(const float2*)&mb2[h * 64 + 2 * lane];

    // prologue staging (parity 0)
    {
        const int nrow0 = (cend - cbeg < BATCH ? cend - cbeg : BATCH) * 5;
        for (int idx = tid; idx < 640; idx += NTHR) {
            int r = idx >> 4;
            if (r < nrow0)
                *(float4*)&Xs[r * 64 + (idx & 15) * 4] =
                    *(const float4*)&g_X[(size_t)(cbeg * 5 + r) * 64 + (idx & 15) * 4];
        }
        if (tid < 64) {
            int w = tid >> 3, j = tid & 7;
            if (j < 5 && cbeg + w < cend)
                wns[tid] = powf(ew[(cbeg + w) * 5 + j], p);
        }
    }

    int par = 0;
    for (int cb = cbeg; cb < cend; cb += BATCH, par ^= 1) {
        __syncthreads();    // staging visible + WAR on A,B

        gemm40h(Xs, W1g, A, lane, wr, wh);   // gate hidden
        gemm40h(Xs, W1m, B, lane, wr, wh);   // msg hidden
        __syncthreads();    // Xs dead; A,B complete

        // gate + softmax + combine (warp-local, reads wns[par]) + prefetch
        {
            const int cb2 = cb + BATCH;
            if (cb2 < cend) {
                const int nrow2 = (cend - cb2 < BATCH ? cend - cb2 : BATCH) * 5;
                for (int idx = tid; idx < 640; idx += NTHR) {
                    int r = idx >> 4;
                    if (r < nrow2)
                        *(float4*)&Xs[r * 64 + (idx & 15) * 4] =
                            *(const float4*)&g_X[(size_t)(cb2 * 5 + r) * 64 + (idx & 15) * 4];
                }
                if (tid < 64) {
                    int w = tid >> 3, j = tid & 7;
                    if (j < 5 && cb2 + w < cend)
                        wns[(par ^ 1) * 64 + tid] = powf(ew[(cb2 + w) * 5 + j], p);
                }
            }

            const int cc = warp;
            if (cb + cc < cend) {
                float w2g_r[8];
                #pragma unroll
                for (int t = 0; t < 8; t++) w2g_r[t] = w2g_s[lane + 32 * t];
                #pragma unroll
                for (int i = 0; i < 5; i++) {
                    float a = 0.f;
                    #pragma unroll
                    for (int t = 0; t < 8; t++) {
                        int k = lane + 32 * t;
                        float hv = A[(cc * 5 + i) * 256 + k] + b1g_s[k];
                        hv = hv >= 0.f ? hv : 0.01f * hv;
                        a += hv * w2g_r[t];
                    }
                    #pragma unroll
                    for (int o = 16; o; o >>= 1) a += __shfl_xor_sync(0xffffffffu, a, o);
                    if (lane == 0) gateb[cc * 32 + i] = a + b2gv;
                }
                __syncwarp();
                if (lane == 0) {
                    float mx = -1e30f;
                    #pragma unroll
                    for (int i = 0; i < 5; i++) mx = fmaxf(mx, gateb[cc * 32 + i]);
                    float v[5], s = 0.f;
                    #pragma unroll
                    for (int i = 0; i < 5; i++) {
                        v[i] = wns[par * 64 + cc * 8 + i] * expf(gateb[cc * 32 + i] - mx);
                        s += v[i];
                    }
                    float inv = 1.f / (s + 1e-10f);
                    float sa = 0.f;
                    #pragma unroll
                    for (int i = 0; i < 5; i++) { float a = v[i] * inv; awb[cc * 32 + i] = a; sa += a; }
                    sas[cc] = sa;
                }
                __syncwarp();

                float a0 = awb[cc * 32 + 0], a1 = awb[cc * 32 + 1], a2 = awb[cc * 32 + 2];
                float a3 = awb[cc * 32 + 3], a4 = awb[cc * 32 + 4];
                #pragma unroll
                for (int t = 0; t < 8; t++) {
                    int k = lane + 32 * t;
                    float bm = b1m_s[k];
                    float hv, g = 0.f;
                    hv = B[(cc * 5 + 0) * 256 + k] + bm; hv = hv >= 0.f ? hv : 0.01f * hv; g += a0 * hv;
                    hv = B[(cc * 5 + 1) * 256 + k] + bm; hv = hv >= 0.f ? hv : 0.01f * hv; g += a1 * hv;
                    hv = B[(cc * 5 + 2) * 256 + k] + bm; hv = hv >= 0.f ? hv : 0.01f * hv; g += a2 * hv;
                    hv = B[(cc * 5 + 3) * 256 + k] + bm; hv = hv >= 0.f ? hv : 0.01f * hv; g += a3 * hv;
                    hv = B[(cc * 5 + 4) * 256 + k] + bm; hv = hv >= 0.f ? hv : 0.01f * hv; g += a4 * hv;
                    GM[cc * 256 + k] = g;     // own-warp target
                }
            }
        }
        __syncwarp();       // GM row is same-warp

        // final GEMM [8,256]@[256,64]: warp reads its own GM row
        {
            ull acc = 0ull;
            #pragma unroll 2
            for (int k4 = 0; k4 < 256; k4 += 4) {
                ull w[4];
                #pragma unroll
                for (int kk = 0; kk < 4; kk++)
                    w[kk] = *(const ull*)&W2h[(k4 + kk) * 64 + 2 * lane];
                F4U g; g.f = *(const float4*)&GM[warp * 256 + k4];
                fma2(acc, dup2(g.s[0]), w[0]);
                fma2(acc, dup2(g.s[1]), w[1]);
                fma2(acc, dup2(g.s[2]), w[2]);
                fma2(acc, dup2(g.s[3]), w[3]);
            }
            if (cb + warp < cend) {
                float2 av = unpack2(acc);
                float sa = sas[warp];
                float2 o = make_float2(av.x + sa * b2r.x, av.y + sa * b2r.y);
                *(float2*)&g_pool[h][(size_t)(cb + warp) * 64 + 2 * lane] = o;
            }
        }
        // no barrier: loop-top __syncthreads covers
    }
}

// ---------------- kernel 5: final head mean ---------------------------------
__global__ void final_combine(float* __restrict__ out) {
    int i = blockIdx.x * 256 + threadIdx.x;
    if (i < CNUM * FDIM)
        out[i] = (g_pool[0][i] + g_pool[1][i] + g_pool[2][i]) * (1.f / 3.f);
}

// ---------------- host launcher ---------------------------------------------
extern "C" void kernel_launch(void* const* d_in, const int* in_sizes, int n_in,
                              void* d_out, int out_size) {
    int wi = 5;
    if (n_in > 5 && in_sizes[5] == 1) wi = 6;

    const float* elem_weights = (const float*)d_in[0];
    const float* elem_fea     = (const float*)d_in[1];
    const float* emb_W = (const float*)d_in[wi + 0];
    const float* emb_b = (const float*)d_in[wi + 1];
    const float* gW1   = (const float*)d_in[wi + 2];
    const float* gb1   = (const float*)d_in[wi + 3];
    const float* gW2   = (const float*)d_in[wi + 4];
    const float* gb2   = (const float*)d_in[wi + 5];
    const float* mW1   = (const float*)d_in[wi + 6];
    const float* mb1   = (const float*)d_in[wi + 7];
    const float* mW2   = (const float*)d_in[wi + 8];
    const float* mb2   = (const float*)d_in[wi + 9];
    const float* gpw   = (const float*)d_in[wi + 10];
    const float* cgW1  = (const float*)d_in[wi + 11];
    const float* cgb1  = (const float*)d_in[wi + 12];
    const float* cgW2  = (const float*)d_in[wi + 13];
    const float* cgb2  = (const float*)d_in[wi + 14];
    const float* cmW1  = (const float*)d_in[wi + 15];
    const float* cmb1  = (const float*)d_in[wi + 16];
    const float* cmW2  = (const float*)d_in[wi + 17];
    const float* cmb2  = (const float*)d_in[wi + 18];
    const float* cpw   = (const float*)d_in[wi + 19];

    cudaFuncSetAttribute(embed_kernel, cudaFuncAttributeMaxDynamicSharedMemorySize, EMB_SMEM);
    cudaFuncSetAttribute(fused_edge,   cudaFuncAttributeMaxDynamicSharedMemorySize, FE_SMEM);
    cudaFuncSetAttribute(fused_pool,   cudaFuncAttributeMaxDynamicSharedMemorySize, FE_SMEM);

    embed_kernel<<<NNODES / 8, 512, EMB_SMEM>>>(elem_fea, emb_W, emb_b, elem_weights);

    for (int l = 0; l < LNUM; l++) {
        fused_edge<<<HNUM * NBLK, NTHR, FE_SMEM>>>(
            gW1 + (size_t)l * HNUM * 128 * 256,
            gb1 + (size_t)l * HNUM * 256,
            gW2 + (size_t)l * HNUM * 256,
            gb2 + (size_t)l * HNUM,
            mW1 + (size_t)l * HNUM * 128 * 256,
            mb1 + (size_t)l * HNUM * 256,
            mW2 + (size_t)l * HNUM * 256 * 64,
            mb2 + (size_t)l * HNUM * 64,
            gpw + (size_t)l * HNUM,
            elem_weights);

        combine_layer<<<(NNODES * FDIM + 255) / 256, 256>>>();
    }

    fused_pool<<<HNUM * NBLK, NTHR, FE_SMEM>>>(cgW1, cgb1, cgW2, cgb2,
                                               cmW1, cmb1, cmW2, cmb2,
                                               cpw, elem_weights);

    final_combine<<<(CNUM * FDIM + 255) / 256, 256>>>((float*)d_out);
}

// round 15
// speedup vs baseline: 1.0708x; 1.0708x over previous
#include <cuda_runtime.h>

// ---------------- problem constants ----------------------------------------
#define CNUM   10000
#define KNUM   5
#define NNODES 50000
#define EMBD   200
#define FDIM   64
#define LNUM   3
#define HNUM   3
#define HID    256

#define NBLK   98        // (layout constant kept; edge/pool use 49 below)
#define EBLK   49        // chunks per head for edge/pool
#define CHUNK  205       // crystals per chunk
#define BATCH  16        // crystals per batch
#define NTHR   512

typedef unsigned long long ull;

__device__ __forceinline__ ull dup2(float x) {
    ull r; asm("mov.b64 %0, {%1, %1};" : "=l"(r) : "f"(x)); return r;
}
__device__ __forceinline__ void fma2(ull &d, ull a, ull b) {
    asm("fma.rn.f32x2 %0, %1, %2, %0;" : "+l"(d) : "l"(a), "l"(b));
}
__device__ __forceinline__ float2 unpack2(ull v) {
    float2 r; asm("mov.b64 {%0, %1}, %2;" : "=f"(r.x), "=f"(r.y) : "l"(v)); return r;
}
union F4U { float4 f; ull u[2]; float s[4]; };

// ---------------- static device scratch ------------------------------------
__device__ float g_X[(size_t)NNODES * FDIM];
__device__ float g_hout[HNUM][(size_t)NNODES * FDIM];
__device__ float g_pool[HNUM][(size_t)CNUM * FDIM];

// ---------------- smem layout (floats) — edge/pool (round-13 proven) -------
#define S_XS   0            // 80 x 64
#define S_A    5120         // 80 x 256
#define S_B    25600        // 80 x 256
#define S_B1G  46080        // 256
#define S_W2G  46336        // 256
#define S_B1M  46592        // 256
#define S_GATE 46848        // 16 x 32
#define S_AW   47360        // 16 x 32
#define S_SAS  47872        // 96
#define S_WNS  47968        // 2 x 128 (parity-buffered; edge uses slot 0 only)
#define S_GM   48224        // 16 x 256 (pool combine target)
#define FE_SMEM ((48224 + 4096 + 32) * 4)

// ---------------- kernel 1: embedding (128 nodes / block, fma2-tiled) ------
// Block: 256 threads = 8 warps; warp owns 16 nodes x 63 cols (lane pair-cols).
// Wsm padded to 64 cols (col 63 = 0); bias likewise; col 63 <- elem_weights.
#define EMB_NB    128
#define EMB_WSM   0                  // 200 x 64 = 12800
#define EMB_BS    12800              // 64
#define EMB_XS    12864              // 128 x 200 = 25600
#define EMB_SMEM  ((12864 + 25600) * 4)
__global__ void __launch_bounds__(256, 1)
embed_kernel(const float* __restrict__ ef,
             const float* __restrict__ W,
             const float* __restrict__ b,
             const float* __restrict__ ew) {
    extern __shared__ float sm[];
    float* Wsm = sm + EMB_WSM;
    float* bs  = sm + EMB_BS;
    float* Xs  = sm + EMB_XS;
    const int tid = threadIdx.x;
    const int warp = tid >> 5, lane = tid & 31;
    const int n0 = blockIdx.x * EMB_NB;
    const int nn = min(EMB_NB, NNODES - n0);

    // stage W padded to 64-col rows; zero pad col 63 via full clear of pad col
    for (int e = tid; e < EMBD; e += 256) Wsm[e * 64 + 63] = 0.f;
    for (int idx = tid; idx < EMBD * 63; idx += 256)
        Wsm[(idx / 63) * 64 + (idx % 63)] = W[idx];
    if (tid < 63) bs[tid] = b[tid];
    if (tid == 63) bs[63] = 0.f;
    // stage X rows (contiguous copy)
    for (int idx = tid; idx < nn * EMBD; idx += 256)
        Xs[idx] = ef[(size_t)n0 * EMBD + idx];
    __syncthreads();

    const int nb = warp * 16;           // first local node of this warp
    ull acc[16];
    {
        ull binit = *(const ull*)&bs[2 * lane];
        #pragma unroll
        for (int i = 0; i < 16; i++) acc[i] = binit;
    }
    for (int e4 = 0; e4 < EMBD; e4 += 4) {
        ull w0 = *(const ull*)&Wsm[(e4 + 0) * 64 + 2 * lane];
        ull w1 = *(const ull*)&Wsm[(e4 + 1) * 64 + 2 * lane];
        ull w2 = *(const ull*)&Wsm[(e4 + 2) * 64 + 2 * lane];
        ull w3 = *(const ull*)&Wsm[(e4 + 3) * 64 + 2 * lane];
        #pragma unroll
        for (int i = 0; i < 16; i++) {
            float4 xv = *(const float4*)&Xs[(nb + i) * EMBD + e4];
            fma2(acc[i], dup2(xv.x), w0);
            fma2(acc[i], dup2(xv.y), w1);
            fma2(acc[i], dup2(xv.z), w2);
            fma2(acc[i], dup2(xv.w), w3);
        }
    }
    #pragma unroll
    for (int i = 0; i < 16; i++) {
        int n = nb + i;
        if (n < nn) {
            float2 o = unpack2(acc[i]);
            if (lane == 31) o.y = ew[n0 + n];   // col 63 = elem_weights
            *(float2*)&g_X[(size_t)(n0 + n) * FDIM + 2 * lane] = o;
        }
    }
}

// ---- gemm80: [80,64] @ [64,256] -> smem; 16 warps: (col-half, row-group) ---
__device__ __noinline__ void gemm80(const float* __restrict__ Xs,
                                    const float* __restrict__ W,
                                    float* __restrict__ out,
                                    int lane, int wr, int wh) {
    const float* Wp = W + wh * 128 + 4 * lane;
    ull acc[10][2];
    #pragma unroll
    for (int i = 0; i < 10; i++) { acc[i][0] = 0ull; acc[i][1] = 0ull; }

    for (int k4 = 0; k4 < 64; k4 += 4) {
        float4 a[10];
        #pragma unroll
        for (int i = 0; i < 10; i++)
            a[i] = *(const float4*)&Xs[(wr + 8 * i) * 64 + k4];
        #pragma unroll
        for (int kk = 0; kk < 4; kk++) {
            F4U w; w.f = *(const float4*)&Wp[(k4 + kk) * 256];
            #pragma unroll
            for (int i = 0; i < 10; i++) {
                float av = kk == 0 ? a[i].x : kk == 1 ? a[i].y : kk == 2 ? a[i].z : a[i].w;
                ull ad = dup2(av);
                fma2(acc[i][0], ad, w.u[0]);
                fma2(acc[i][1], ad, w.u[1]);
            }
        }
    }
    #pragma unroll
    for (int i = 0; i < 10; i++) {
        F4U o;
        o.u[0] = acc[i][0]; o.u[1] = acc[i][1];
        *(float4*)&out[(wr + 8 * i) * 256 + wh * 128 + 4 * lane] = o.f;
    }
}

// ---------------- kernel 2: fused proj + edge attention --------------------
__global__ void __launch_bounds__(NTHR, 1)
fused_edge(const float* __restrict__ gW1, const float* __restrict__ gb1,
           const float* __restrict__ gW2, const float* __restrict__ gb2,
           const float* __restrict__ mW1, const float* __restrict__ mb1,
           const float* __restrict__ mW2, const float* __restrict__ mb2,
           const float* __restrict__ gpow, const float* __restrict__ ew) {
    extern __shared__ float sm[];
    float* Xs    = sm + S_XS;
    float* A     = sm + S_A;
    float* B     = sm + S_B;
    float* b1g_s = sm + S_B1G;
    float* w2g_s = sm + S_W2G;
    float* b1m_s = sm + S_B1M;
    float* gateb = sm + S_GATE;
    float* awb   = sm + S_AW;
    float* sas   = sm + S_SAS;
    float* wns   = sm + S_WNS;

    const int tid  = threadIdx.x;
    const int warp = tid >> 5, lane = tid & 31;
    const int wr = warp & 7, wh = warp >> 3;
    const int h     = blockIdx.x / EBLK;
    const int chunk = blockIdx.x % EBLK;
    const int cbeg = chunk * CHUNK;
    const int cend = min(cbeg + CHUNK, CNUM);

    const float* WgA = gW1 + (size_t)h * 128 * 256;
    const float* WgB = WgA + 64 * 256;
    const float* WmA = mW1 + (size_t)h * 128 * 256;
    const float* WmB = WmA + 64 * 256;
    const float* W2h = mW2 + (size_t)h * 256 * 64;

    if (tid < 256) {
        b1g_s[tid] = gb1[h * 256 + tid];
        w2g_s[tid] = gW2[h * 256 + tid];
        b1m_s[tid] = mb1[h * 256 + tid];
    }
    const float p    = gpow[h];
    const float b2gv = gb2[h];
    const float2 b2r = *(const float2*)&mb2[h * 64 + 2 * lane];
    float* hout = g_hout[h];

    // prologue: stage first batch (all threads)
    {
        const int nrow0 = (cend - cbeg < BATCH ? cend - cbeg : BATCH) * 5;
        for (int idx = tid; idx < 1280; idx += NTHR) {
            int r = idx >> 4;
            if (r < nrow0)
                *(float4*)&Xs[r * 64 + (idx & 15) * 4] =
                    *(const float4*)&g_X[(size_t)(cbeg * 5 + r) * 64 + (idx & 15) * 4];
        }
        if (tid < 128) {
            int w = tid >> 3, j = tid & 7;
            if (j < 5 && cbeg + w < cend)
                wns[tid] = powf(ew[(cbeg + w) * 5 + j], p);
        }
    }

    for (int cb = cbeg; cb < cend; cb += BATCH) {
        __syncthreads();   // staging visible + WAR on A,B from prev final gemm

        // gate projections
        gemm80(Xs, WgA, A, lane, wr, wh);
        gemm80(Xs, WgB, B, lane, wr, wh);
        __syncthreads();

        // gate + softmax: warp <-> crystal; B rows cached in registers
        {
            const int cc = warp;
            if (cb + cc < cend) {
                float w2g_r[8], b_r[5][8];
                #pragma unroll
                for (int t = 0; t < 8; t++) w2g_r[t] = w2g_s[lane + 32 * t];
                #pragma unroll
                for (int j = 0; j < 5; j++)
                    #pragma unroll
                    for (int t = 0; t < 8; t++)
                        b_r[j][t] = B[(cc * 5 + j) * 256 + lane + 32 * t];
                #pragma unroll
                for (int i = 0; i < 5; i++) {
                    float gsr[8];
                    #pragma unroll
                    for (int t = 0; t < 8; t++) {
                        int k = lane + 32 * t;
                        gsr[t] = A[(cc * 5 + i) * 256 + k] + b1g_s[k];
                    }
                    #pragma unroll
                    for (int j = 0; j < 5; j++) {
                        float a = 0.f;
                        #pragma unroll
                        for (int t = 0; t < 8; t++) {
                            float hv = gsr[t] + b_r[j][t];
                            hv = hv >= 0.f ? hv : 0.01f * hv;
                            a += hv * w2g_r[t];
                        }
                        #pragma unroll
                        for (int o = 16; o; o >>= 1) a += __shfl_xor_sync(0xffffffffu, a, o);
                        if (lane == 0) gateb[cc * 32 + i * 5 + j] = a + b2gv;
                    }
                }
                __syncwarp();
                if (lane < 5) {
                    int i = lane;
                    float mx = -1e30f;
                    #pragma unroll
                    for (int j = 0; j < 5; j++) mx = fmaxf(mx, gateb[cc * 32 + i * 5 + j]);
                    float v[5], s = 0.f;
                    #pragma unroll
                    for (int j = 0; j < 5; j++) {
                        v[j] = wns[cc * 8 + j] * expf(gateb[cc * 32 + i * 5 + j] - mx);
                        s += v[j];
                    }
                    float inv = 1.f / (s + 1e-10f);
                    float sa = 0.f;
                    #pragma unroll
                    for (int j = 0; j < 5; j++) { float a = v[j] * inv; awb[cc * 32 + i * 5 + j] = a; sa += a; }
                    sas[cc * 5 + i] = sa;
                }
            }
        }
        __syncthreads();

        // msg projections (overwrite A,B)
        gemm80(Xs, WmA, A, lane, wr, wh);
        gemm80(Xs, WmB, B, lane, wr, wh);
        __syncthreads();   // Xs now dead for this batch

        // overlap phase: prefetch next batch's X/wns + G build (warp-local)
        {
            const int cb2 = cb + BATCH;
            if (cb2 < cend) {
                const int nrow2 = (cend - cb2 < BATCH ? cend - cb2 : BATCH) * 5;
                for (int idx = tid; idx < 1280; idx += NTHR) {
                    int r = idx >> 4;
                    if (r < nrow2)
                        *(float4*)&Xs[r * 64 + (idx & 15) * 4] =
                            *(const float4*)&g_X[(size_t)(cb2 * 5 + r) * 64 + (idx & 15) * 4];
                }
                if (tid < 128) {
                    int w = tid >> 3, j = tid & 7;
                    if (j < 5 && cb2 + w < cend)
                        wns[tid] = powf(ew[(cb2 + w) * 5 + j], p);
                }
            }

            const int cc = warp;
            if (cb + cc < cend) {
                float a_r[25];
                #pragma unroll
                for (int q = 0; q < 25; q++) a_r[q] = awb[cc * 32 + q];
                #pragma unroll
                for (int t = 0; t < 8; t++) {
                    int k = lane + 32 * t;
                    float bm = b1m_s[k];
                    float s0 = A[(cc * 5 + 0) * 256 + k] + bm;
                    float s1 = A[(cc * 5 + 1) * 256 + k] + bm;
                    float s2 = A[(cc * 5 + 2) * 256 + k] + bm;
                    float s3 = A[(cc * 5 + 3) * 256 + k] + bm;
                    float s4 = A[(cc * 5 + 4) * 256 + k] + bm;
                    float g0 = 0.f, g1 = 0.f, g2 = 0.f, g3 = 0.f, g4 = 0.f;
                    #pragma unroll
                    for (int j = 0; j < 5; j++) {
                        float nb = B[(cc * 5 + j) * 256 + k];
                        float hv;
                        hv = s0 + nb; hv = hv >= 0.f ? hv : 0.01f * hv; g0 += a_r[0 * 5 + j] * hv;
                        hv = s1 + nb; hv = hv >= 0.f ? hv : 0.01f * hv; g1 += a_r[1 * 5 + j] * hv;
                        hv = s2 + nb; hv = hv >= 0.f ? hv : 0.01f * hv; g2 += a_r[2 * 5 + j] * hv;
                        hv = s3 + nb; hv = hv >= 0.f ? hv : 0.01f * hv; g3 += a_r[3 * 5 + j] * hv;
                        hv = s4 + nb; hv = hv >= 0.f ? hv : 0.01f * hv; g4 += a_r[4 * 5 + j] * hv;
                    }
                    A[(cc * 5 + 0) * 256 + k] = g0;
                    A[(cc * 5 + 1) * 256 + k] = g1;
                    A[(cc * 5 + 2) * 256 + k] = g2;
                    A[(cc * 5 + 3) * 256 + k] = g3;
                    A[(cc * 5 + 4) * 256 + k] = g4;
                }
            }
        }
        __syncwarp();      // G rows are same-warp: no CTA barrier needed

        // final GEMM: warp owns its crystal's 5 G rows (written by itself)
        {
            ull acc[5];
            #pragma unroll
            for (int i = 0; i < 5; i++) acc[i] = 0ull;
            #pragma unroll 2
            for (int k4 = 0; k4 < 256; k4 += 4) {
                ull w[4];
                #pragma unroll
                for (int kk = 0; kk < 4; kk++)
                    w[kk] = *(const ull*)&W2h[(k4 + kk) * 64 + 2 * lane];
                #pragma unroll
                for (int i = 0; i < 5; i++) {
                    F4U g; g.f = *(const float4*)&A[(5 * warp + i) * 256 + k4];
                    fma2(acc[i], dup2(g.s[0]), w[0]);
                    fma2(acc[i], dup2(g.s[1]), w[1]);
                    fma2(acc[i], dup2(g.s[2]), w[2]);
                    fma2(acc[i], dup2(g.s[3]), w[3]);
                }
            }
            if (cb + warp < cend) {
                #pragma unroll
                for (int i = 0; i < 5; i++) {
                    int r = 5 * warp + i;
                    float2 av = unpack2(acc[i]);
                    float sa = sas[r];
                    float2 o = make_float2(av.x + sa * b2r.x, av.y + sa * b2r.y);
                    *(float2*)&hout[(size_t)(cb * 5 + r) * 64 + 2 * lane] = o;
                }
            }
        }
        // no barrier: loop-top __syncthreads covers WAR on A,B and staging
    }
}

// ---------------- kernel 3: residual combine over heads --------------------
__global__ void combine_layer() {
    size_t i = (size_t)blockIdx.x * 256 + threadIdx.x;
    if (i < (size_t)NNODES * FDIM)
        g_X[i] += (g_hout[0][i] + g_hout[1][i] + g_hout[2][i]) * (1.f / 3.f);
}

// ---------------- kernel 4: fused proj + pool ------------------------------
__global__ void __launch_bounds__(NTHR, 1)
fused_pool(const float* __restrict__ gW1, const float* __restrict__ gb1,
           const float* __restrict__ gW2, const float* __restrict__ gb2,
           const float* __restrict__ mW1, const float* __restrict__ mb1,
           const float* __restrict__ mW2, const float* __restrict__ mb2,
           const float* __restrict__ cpow, const float* __restrict__ ew) {
    extern __shared__ float sm[];
    float* Xs    = sm + S_XS;
    float* A     = sm + S_A;
    float* B     = sm + S_B;
    float* b1g_s = sm + S_B1G;
    float* w2g_s = sm + S_W2G;
    float* b1m_s = sm + S_B1M;
    float* gateb = sm + S_GATE;
    float* awb   = sm + S_AW;
    float* sas   = sm + S_SAS;
    float* wns   = sm + S_WNS;   // 2 x 128: read slot par, prefetch writes par^1
    float* GM    = sm + S_GM;

    const int tid  = threadIdx.x;
    const int warp = tid >> 5, lane = tid & 31;
    const int wr = warp & 7, wh = warp >> 3;
    const int h     = blockIdx.x / EBLK;
    const int chunk = blockIdx.x % EBLK;
    const int cbeg = chunk * CHUNK;
    const int cend = min(cbeg + CHUNK, CNUM);

    const float* W1g = gW1 + (size_t)h * 64 * 256;
    const float* W1m = mW1 + (size_t)h * 64 * 256;
    const float* W2h = mW2 + (size_t)h * 256 * 64;

    if (tid < 256) {
        b1g_s[tid] = gb1[h * 256 + tid];
        w2g_s[tid] = gW2[h * 256 + tid];
        b1m_s[tid] = mb1[h * 256 + tid];
    }
    const float p    = cpow[h];
    const float b2gv = gb2[h];
    const float2 b2r = *(const float2*)&mb2[h * 64 + 2 * lane];

    // prologue staging (parity 0)
    {
        const int nrow0 = (cend - cbeg < BATCH ? cend - cbeg : BATCH) * 5;
        for (int idx = tid; idx < 1280; idx += NTHR) {
            int r = idx >> 4;
            if (r < nrow0)
                *(float4*)&Xs[r * 64 + (idx & 15) * 4] =
                    *(const float4*)&g_X[(size_t)(cbeg * 5 + r) * 64 + (idx & 15) * 4];
        }
        if (tid < 128) {
            int w = tid >> 3, j = tid & 7;
            if (j < 5 && cbeg + w < cend)
                wns[tid] = powf(ew[(cbeg + w) * 5 + j], p);
        }
    }

    int par = 0;
    for (int cb = cbeg; cb < cend; cb += BATCH, par ^= 1) {
        __syncthreads();    // staging visible + WAR on A,B

        gemm80(Xs, W1g, A, lane, wr, wh);   // gate hidden
        gemm80(Xs, W1m, B, lane, wr, wh);   // msg hidden
        __syncthreads();    // Xs dead; A,B complete

        // gate + softmax + combine (warp-local, reads wns[par]) + prefetch
        {
            const int cb2 = cb + BATCH;
            if (cb2 < cend) {
                const int nrow2 = (cend - cb2 < BATCH ? cend - cb2 : BATCH) * 5;
                for (int idx = tid; idx < 1280; idx += NTHR) {
                    int r = idx >> 4;
                    if (r < nrow2)
                        *(float4*)&Xs[r * 64 + (idx & 15) * 4] =
                            *(const float4*)&g_X[(size_t)(cb2 * 5 + r) * 64 + (idx & 15) * 4];
                }
                if (tid < 128) {
                    int w = tid >> 3, j = tid & 7;
                    if (j < 5 && cb2 + w < cend)
                        wns[(par ^ 1) * 128 + tid] = powf(ew[(cb2 + w) * 5 + j], p);
                }
            }

            const int cc = warp;
            if (cb + cc < cend) {
                float w2g_r[8];
                #pragma unroll
                for (int t = 0; t < 8; t++) w2g_r[t] = w2g_s[lane + 32 * t];
                #pragma unroll
                for (int i = 0; i < 5; i++) {
                    float a = 0.f;
                    #pragma unroll
                    for (int t = 0; t < 8; t++) {
                        int k = lane + 32 * t;
                        float hv = A[(cc * 5 + i) * 256 + k] + b1g_s[k];
                        hv = hv >= 0.f ? hv : 0.01f * hv;
                        a += hv * w2g_r[t];
                    }
                    #pragma unroll
                    for (int o = 16; o; o >>= 1) a += __shfl_xor_sync(0xffffffffu, a, o);
                    if (lane == 0) gateb[cc * 32 + i] = a + b2gv;
                }
                __syncwarp();
                if (lane == 0) {
                    float mx = -1e30f;
                    #pragma unroll
                    for (int i = 0; i < 5; i++) mx = fmaxf(mx, gateb[cc * 32 + i]);
                    float v[5], s = 0.f;
                    #pragma unroll
                    for (int i = 0; i < 5; i++) {
                        v[i] = wns[par * 128 + cc * 8 + i] * expf(gateb[cc * 32 + i] - mx);
                        s += v[i];
                    }
                    float inv = 1.f / (s + 1e-10f);
                    float sa = 0.f;
                    #pragma unroll
                    for (int i = 0; i < 5; i++) { float a = v[i] * inv; awb[cc * 32 + i] = a; sa += a; }
                    sas[cc] = sa;
                }
                __syncwarp();

                float a0 = awb[cc * 32 + 0], a1 = awb[cc * 32 + 1], a2 = awb[cc * 32 + 2];
                float a3 = awb[cc * 32 + 3], a4 = awb[cc * 32 + 4];
                #pragma unroll
                for (int t = 0; t < 8; t++) {
                    int k = lane + 32 * t;
                    float bm = b1m_s[k];
                    float hv, g = 0.f;
                    hv = B[(cc * 5 + 0) * 256 + k] + bm; hv = hv >= 0.f ? hv : 0.01f * hv; g += a0 * hv;
                    hv = B[(cc * 5 + 1) * 256 + k] + bm; hv = hv >= 0.f ? hv : 0.01f * hv; g += a1 * hv;
                    hv = B[(cc * 5 + 2) * 256 + k] + bm; hv = hv >= 0.f ? hv : 0.01f * hv; g += a2 * hv;
                    hv = B[(cc * 5 + 3) * 256 + k] + bm; hv = hv >= 0.f ? hv : 0.01f * hv; g += a3 * hv;
                    hv = B[(cc * 5 + 4) * 256 + k] + bm; hv = hv >= 0.f ? hv : 0.01f * hv; g += a4 * hv;
                    GM[cc * 256 + k] = g;     // own-warp target
                }
            }
        }
        __syncwarp();       // GM row is same-warp

        // final GEMM [16,256]@[256,64]: warp reads its own GM row
        {
            ull acc = 0ull;
            #pragma unroll 2
            for (int k4 = 0; k4 < 256; k4 += 4) {
                ull w[4];
                #pragma unroll
                for (int kk = 0; kk < 4; kk++)
                    w[kk] = *(const ull*)&W2h[(k4 + kk) * 64 + 2 * lane];
                F4U g; g.f = *(const float4*)&GM[warp * 256 + k4];
                fma2(acc, dup2(g.s[0]), w[0]);
                fma2(acc, dup2(g.s[1]), w[1]);
                fma2(acc, dup2(g.s[2]), w[2]);
                fma2(acc, dup2(g.s[3]), w[3]);
            }
            if (cb + warp < cend) {
                float2 av = unpack2(acc);
                float sa = sas[warp];
                float2 o = make_float2(av.x + sa * b2r.x, av.y + sa * b2r.y);
                *(float2*)&g_pool[h][(size_t)(cb + warp) * 64 + 2 * lane] = o;
            }
        }
        // no barrier: loop-top __syncthreads covers
    }
}

// ---------------- kernel 5: final head mean ---------------------------------
__global__ void final_combine(float* __restrict__ out) {
    int i = blockIdx.x * 256 + threadIdx.x;
    if (i < CNUM * FDIM)
        out[i] = (g_pool[0][i] + g_pool[1][i] + g_pool[2][i]) * (1.f / 3.f);
}

// ---------------- host launcher ---------------------------------------------
extern "C" void kernel_launch(void* const* d_in, const int* in_sizes, int n_in,
                              void* d_out, int out_size) {
    int wi = 5;
    if (n_in > 5 && in_sizes[5] == 1) wi = 6;

    const float* elem_weights = (const float*)d_in[0];
    const float* elem_fea     = (const float*)d_in[1];
    const float* emb_W = (const float*)d_in[wi + 0];
    const float* emb_b = (const float*)d_in[wi + 1];
    const float* gW1   = (const float*)d_in[wi + 2];
    const float* gb1   = (const float*)d_in[wi + 3];
    const float* gW2   = (const float*)d_in[wi + 4];
    const float* gb2   = (const float*)d_in[wi + 5];
    const float* mW1   = (const float*)d_in[wi + 6];
    const float* mb1   = (const float*)d_in[wi + 7];
    const float* mW2   = (const float*)d_in[wi + 8];
    const float* mb2   = (const float*)d_in[wi + 9];
    const float* gpw   = (const float*)d_in[wi + 10];
    const float* cgW1  = (const float*)d_in[wi + 11];
    const float* cgb1  = (const float*)d_in[wi + 12];
    const float* cgW2  = (const float*)d_in[wi + 13];
    const float* cgb2  = (const float*)d_in[wi + 14];
    const float* cmW1  = (const float*)d_in[wi + 15];
    const float* cmb1  = (const float*)d_in[wi + 16];
    const float* cmW2  = (const float*)d_in[wi + 17];
    const float* cmb2  = (const float*)d_in[wi + 18];
    const float* cpw   = (const float*)d_in[wi + 19];

    cudaFuncSetAttribute(embed_kernel, cudaFuncAttributeMaxDynamicSharedMemorySize, EMB_SMEM);
    cudaFuncSetAttribute(fused_edge,   cudaFuncAttributeMaxDynamicSharedMemorySize, FE_SMEM);
    cudaFuncSetAttribute(fused_pool,   cudaFuncAttributeMaxDynamicSharedMemorySize, FE_SMEM);

    embed_kernel<<<(NNODES + EMB_NB - 1) / EMB_NB, 256, EMB_SMEM>>>(
        elem_fea, emb_W, emb_b, elem_weights);

    for (int l = 0; l < LNUM; l++) {
        fused_edge<<<HNUM * EBLK, NTHR, FE_SMEM>>>(
            gW1 + (size_t)l * HNUM * 128 * 256,
            gb1 + (size_t)l * HNUM * 256,
            gW2 + (size_t)l * HNUM * 256,
            gb2 + (size_t)l * HNUM,
            mW1 + (size_t)l * HNUM * 128 * 256,
            mb1 + (size_t)l * HNUM * 256,
            mW2 + (size_t)l * HNUM * 256 * 64,
            mb2 + (size_t)l * HNUM * 64,
            gpw + (size_t)l * HNUM,
            elem_weights);

        combine_layer<<<(NNODES * FDIM + 255) / 256, 256>>>();
    }

    fused_pool<<<HNUM * EBLK, NTHR, FE_SMEM>>>(cgW1, cgb1, cgW2, cgb2,
                                               cmW1, cmb1, cmW2, cmb2,
                                               cpw, elem_weights);

    final_combine<<<(CNUM * FDIM + 255) / 256, 256>>>((float*)d_out);
}